// round 8
// baseline (speedup 1.0000x reference)
#include <cuda_runtime.h>
#include <cfloat>
#include <math.h>

#define NX 12288
#define NYTOT 12288
#define DD 256
#define KSEL 30
#define SPLITS 3
#define NYS (NYTOT / SPLITS)      // 4096
#define BM 128
#define BN 128
#define BKC 8
#define NST (DD / BKC)            // 32 k-stages

// scratch (no allocations allowed)
__device__ float g_XnA[NX * DD];
__device__ float g_YnA[NYTOT * DD];
__device__ float g_XnB[NX * DD];
__device__ float g_YnB[NYTOT * DD];
__device__ float g_pvA[NX * SPLITS * 2 * KSEL];
__device__ int   g_piA[NX * SPLITS * 2 * KSEL];
__device__ float g_pvB[NX * SPLITS * 2 * KSEL];
__device__ int   g_piB[NX * SPLITS * 2 * KSEL];

__device__ __forceinline__ float rcp_approx(float b) {
    float r;
    asm("rcp.approx.f32 %0, %1;" : "=f"(r) : "f"(b));
    return r;
}

// ---------------------------------------------------------------------------
// Canonical XLA/Triton 128-thread row reduction (established shape):
// per-thread partial p = add(mul(ex,ex), mul(ey,ey)) over contiguous vec2;
// intra-warp xor tree 16..1; 4 warp sums -> shared; warp0 (lane<4 else 0)
// xor tree; m = max(sqrt_rn(total), 1e-8) broadcast.
// ---------------------------------------------------------------------------
__device__ __forceinline__ float row_m_128(float p, int t, float* sw, float* smv) {
    int lane = t & 31;
    int warp = t >> 5;
    #pragma unroll
    for (int o = 16; o > 0; o >>= 1)
        p = __fadd_rn(p, __shfl_xor_sync(0xffffffffu, p, o));
    if (lane == 0) sw[warp] = p;
    __syncthreads();
    if (warp == 0) {
        float v = (lane < 4) ? sw[lane] : 0.0f;
        #pragma unroll
        for (int o = 16; o > 0; o >>= 1)
            v = __fadd_rn(v, __shfl_xor_sync(0xffffffffu, v, o));
        if (lane == 0)
            *smv = fmaxf(__fsqrt_rn(v), 1e-8f);
    }
    __syncthreads();
    return *smv;
}

// Pipeline A (-> out0 probe): rcp.approx multiply
__global__ __launch_bounds__(128)
void normA_kernel(const float* __restrict__ X, const float* __restrict__ Y) {
    __shared__ float sw[4];
    __shared__ float smv;
    int row = blockIdx.x;
    const float* src;
    float* dst;
    if (row < NX) { src = X + (size_t)row * DD; dst = g_XnA + (size_t)row * DD; }
    else { int r = row - NX; src = Y + (size_t)r * DD; dst = g_YnA + (size_t)r * DD; }

    int t = threadIdx.x;
    float2 e = *(const float2*)(src + 2 * t);
    float p = __fadd_rn(__fmul_rn(e.x, e.x), __fmul_rn(e.y, e.y));
    float m = row_m_128(p, t, sw, &smv);
    float inv = rcp_approx(m);
    float2 o;
    o.x = __fmul_rn(e.x, inv);
    o.y = __fmul_rn(e.y, inv);
    *(float2*)(dst + 2 * t) = o;
}

// Pipeline B (-> out2 attempt): correctly-rounded reciprocal multiply
__global__ __launch_bounds__(128)
void normB_kernel(const float* __restrict__ X, const float* __restrict__ Y) {
    __shared__ float sw[4];
    __shared__ float smv;
    int row = blockIdx.x;
    const float* src;
    float* dst;
    if (row < NX) { src = X + (size_t)row * DD; dst = g_XnB + (size_t)row * DD; }
    else { int r = row - NX; src = Y + (size_t)r * DD; dst = g_YnB + (size_t)r * DD; }

    int t = threadIdx.x;
    float2 e = *(const float2*)(src + 2 * t);
    float p = __fadd_rn(__fmul_rn(e.x, e.x), __fmul_rn(e.y, e.y));
    float m = row_m_128(p, t, sw, &smv);
    float inv = __fdiv_rn(1.0f, m);
    float2 o;
    o.x = __fmul_rn(e.x, inv);
    o.y = __fmul_rn(e.y, inv);
    *(float2*)(dst + 2 * t) = o;
}

// ---------------------------------------------------------------------------
// Fused SGEMM (128x128 tile, fp32) + running per-row top-30.
// Single ascending-k FMA chain per element (bitwise = cublas/triton sgemm).
// ---------------------------------------------------------------------------
__global__ __launch_bounds__(256, 2)
void simtopk_kernel(const float* __restrict__ Xn, const float* __restrict__ Yn,
                    float* __restrict__ pv, int* __restrict__ pi) {
    extern __shared__ float sm[];
    float* As = sm;                    // [2][BKC][BM]
    float* Bs = sm + 2 * BKC * BM;     // [2][BKC][BN]
    float* Cs = sm;                    // [BM][BN+1]

    const int t = threadIdx.x;
    const int mbase = blockIdx.x * BM;
    const int sp = blockIdx.y;
    const int tx = t & 15;
    const int ty = t >> 4;
    const int lr = t & 127;
    const int lh = t >> 7;
    const int lrow = t >> 1;
    const int lk4  = (t & 1) * 4;

    float kv[KSEL];
    int   ki[KSEL];
    #pragma unroll
    for (int j = 0; j < KSEL; j++) { kv[j] = -FLT_MAX; ki[j] = 0x7fffffff; }
    float kth = -FLT_MAX;

    const float* Aptr = Xn + (size_t)(mbase + lrow) * DD + lk4;

    #pragma unroll 1
    for (int nt = 0; nt < NYS / BN; nt++) {
        const int nbase = sp * NYS + nt * BN;
        const float* Bptr = Yn + (size_t)(nbase + lrow) * DD + lk4;

        float acc[8][8];
        #pragma unroll
        for (int i = 0; i < 8; i++)
            #pragma unroll
            for (int j = 0; j < 8; j++) acc[i][j] = 0.0f;

        {
            float4 a4 = *(const float4*)Aptr;
            float4 b4 = *(const float4*)Bptr;
            As[(lk4 + 0) * BM + lrow] = a4.x;
            As[(lk4 + 1) * BM + lrow] = a4.y;
            As[(lk4 + 2) * BM + lrow] = a4.z;
            As[(lk4 + 3) * BM + lrow] = a4.w;
            Bs[(lk4 + 0) * BN + lrow] = b4.x;
            Bs[(lk4 + 1) * BN + lrow] = b4.y;
            Bs[(lk4 + 2) * BN + lrow] = b4.z;
            Bs[(lk4 + 3) * BN + lrow] = b4.w;
        }
        __syncthreads();

        #pragma unroll 1
        for (int ksg = 0; ksg < NST; ksg++) {
            float4 na4, nb4;
            const bool more = (ksg + 1 < NST);
            if (more) {
                na4 = *(const float4*)(Aptr + (ksg + 1) * BKC);
                nb4 = *(const float4*)(Bptr + (ksg + 1) * BKC);
            }
            const float* Ac = As + (ksg & 1) * BKC * BM;
            const float* Bc = Bs + (ksg & 1) * BKC * BN;
            #pragma unroll
            for (int kk = 0; kk < BKC; kk++) {
                float a[8], b[8];
                *(float4*)(a)     = *(const float4*)(Ac + kk * BM + ty * 8);
                *(float4*)(a + 4) = *(const float4*)(Ac + kk * BM + ty * 8 + 4);
                *(float4*)(b)     = *(const float4*)(Bc + kk * BN + tx * 8);
                *(float4*)(b + 4) = *(const float4*)(Bc + kk * BN + tx * 8 + 4);
                #pragma unroll
                for (int i = 0; i < 8; i++)
                    #pragma unroll
                    for (int j = 0; j < 8; j++)
                        acc[i][j] = __fmaf_rn(a[i], b[j], acc[i][j]);
            }
            if (more) {
                float* An = As + ((ksg + 1) & 1) * BKC * BM;
                float* Bn = Bs + ((ksg + 1) & 1) * BKC * BN;
                An[(lk4 + 0) * BM + lrow] = na4.x;
                An[(lk4 + 1) * BM + lrow] = na4.y;
                An[(lk4 + 2) * BM + lrow] = na4.z;
                An[(lk4 + 3) * BM + lrow] = na4.w;
                Bn[(lk4 + 0) * BN + lrow] = nb4.x;
                Bn[(lk4 + 1) * BN + lrow] = nb4.y;
                Bn[(lk4 + 2) * BN + lrow] = nb4.z;
                Bn[(lk4 + 3) * BN + lrow] = nb4.w;
            }
            __syncthreads();
        }

        #pragma unroll
        for (int i = 0; i < 8; i++)
            #pragma unroll
            for (int j = 0; j < 8; j++)
                Cs[(ty * 8 + i) * (BN + 1) + tx * 8 + j] = acc[i][j];
        __syncthreads();

        {
            const float* crow = Cs + lr * (BN + 1) + lh * 64;
            const int gbase = nbase + lh * 64;
            #pragma unroll 1
            for (int j = 0; j < 64; j++) {
                float v = crow[j];
                if (v > kth) {
                    int p = KSEL - 1;
                    while (p > 0 && kv[p - 1] < v) {
                        kv[p] = kv[p - 1];
                        ki[p] = ki[p - 1];
                        p--;
                    }
                    kv[p] = v;
                    ki[p] = gbase + j;
                    kth = kv[KSEL - 1];
                }
            }
        }
        __syncthreads();
    }

    {
        const int row = mbase + lr;
        const size_t base = ((size_t)(row * SPLITS + sp) * 2 + lh) * KSEL;
        #pragma unroll 1
        for (int j = 0; j < KSEL; j++) {
            pv[base + j] = kv[j];
            pi[base + j] = ki[j];
        }
    }
}

// ---------------------------------------------------------------------------
// Merge; out0 (values) from A (probe), out2 (v) from B (attempt).
// ---------------------------------------------------------------------------
__device__ __forceinline__ void merge_row(int r, const float* __restrict__ pvg,
                                          const int* __restrict__ pig,
                                          float* mv, int* mi) {
    #pragma unroll
    for (int j = 0; j < KSEL; j++) { mv[j] = -FLT_MAX; mi[j] = 0x7fffffff; }
    for (int l = 0; l < SPLITS * 2; l++) {
        const size_t base = ((size_t)r * SPLITS * 2 + l) * KSEL;
        for (int e = 0; e < KSEL; e++) {
            float v = pvg[base + e];
            int idx = pig[base + e];
            float lv = mv[KSEL - 1];
            int   li = mi[KSEL - 1];
            bool better = (v > lv) || (v == lv && idx < li);
            if (!better) break;
            int p = KSEL - 1;
            while (p > 0 && (v > mv[p - 1] || (v == mv[p - 1] && idx < mi[p - 1]))) {
                mv[p] = mv[p - 1];
                mi[p] = mi[p - 1];
                p--;
            }
            mv[p] = v;
            mi[p] = idx;
        }
    }
}

__global__ void merge_kernel(float* __restrict__ out) {
    int r = blockIdx.x * blockDim.x + threadIdx.x;
    if (r >= NX) return;
    float mv[KSEL];
    int   mi[KSEL];
    const size_t NK = (size_t)NX * KSEL;

    // A -> values (out0): rcp.approx probe
    merge_row(r, g_pvA, g_piA, mv, mi);
    #pragma unroll 1
    for (int j = 0; j < KSEL; j++)
        out[(size_t)r * KSEL + j] = mv[j];

    // u (out1): exact
    #pragma unroll 1
    for (int j = 0; j < KSEL; j++)
        out[NK + (size_t)r * KSEL + j] = (float)r;

    // B -> v (out2): recip-rn multiply attempt
    merge_row(r, g_pvB, g_piB, mv, mi);
    #pragma unroll 1
    for (int j = 0; j < KSEL; j++)
        out[2 * NK + (size_t)r * KSEL + j] = (float)mi[j];
}

extern "C" void kernel_launch(void* const* d_in, const int* in_sizes, int n_in,
                              void* d_out, int out_size) {
    const float* X = (const float*)d_in[0];
    const float* Y = (const float*)d_in[1];
    float* out = (float*)d_out;

    const int smem_bytes = BM * (BN + 1) * 4;   // 66048 (>48KB -> opt-in)
    cudaFuncSetAttribute(simtopk_kernel,
                         cudaFuncAttributeMaxDynamicSharedMemorySize, smem_bytes);

    normA_kernel<<<NX + NYTOT, 128>>>(X, Y);
    normB_kernel<<<NX + NYTOT, 128>>>(X, Y);

    dim3 grid(NX / BM, SPLITS);
    {
        float *pvA, *pvB; int *piA, *piB;
        float *xnA, *ynA, *xnB, *ynB;
        cudaGetSymbolAddress((void**)&pvA, g_pvA);
        cudaGetSymbolAddress((void**)&piA, g_piA);
        cudaGetSymbolAddress((void**)&pvB, g_pvB);
        cudaGetSymbolAddress((void**)&piB, g_piB);
        cudaGetSymbolAddress((void**)&xnA, g_XnA);
        cudaGetSymbolAddress((void**)&ynA, g_YnA);
        cudaGetSymbolAddress((void**)&xnB, g_XnB);
        cudaGetSymbolAddress((void**)&ynB, g_YnB);
        simtopk_kernel<<<grid, 256, smem_bytes>>>(xnA, ynA, pvA, piA);
        simtopk_kernel<<<grid, 256, smem_bytes>>>(xnB, ynB, pvB, piB);
    }

    merge_kernel<<<(NX + 255) / 256, 256>>>(out);
}

// round 9
// speedup vs baseline: 2.1338x; 2.1338x over previous
#include <cuda_runtime.h>
#include <cfloat>
#include <math.h>

#define NX 12288
#define NYTOT 12288
#define DD 256
#define KSEL 30
#define SPLITS 3
#define NYS (NYTOT / SPLITS)      // 4096
#define BM 128
#define BN 128
#define BKC 16
#define NST (DD / BKC)            // 16 k-stages

// scratch (no allocations allowed)
__device__ float g_Xn[NX * DD];
__device__ float g_Yn[NYTOT * DD];
__device__ float g_pv[NX * SPLITS * 2 * KSEL];
__device__ int   g_pi[NX * SPLITS * 2 * KSEL];

// ---------------------------------------------------------------------------
// Row-normalize (validated R8-B numerics):
// 128-thread row, vec2 partial add(mul,mul); warp xor tree 16..1; 4 warp sums
// -> shared; warp0 (lane<4 else 0) xor tree; m = max(sqrt_rn, 1e-8);
// inv = div_rn(1, m); out = x * inv.
// ---------------------------------------------------------------------------
__global__ __launch_bounds__(128)
void norm_kernel(const float* __restrict__ X, const float* __restrict__ Y) {
    __shared__ float sw[4];
    __shared__ float smv;
    int row = blockIdx.x;
    const float* src;
    float* dst;
    if (row < NX) { src = X + (size_t)row * DD; dst = g_Xn + (size_t)row * DD; }
    else { int r = row - NX; src = Y + (size_t)r * DD; dst = g_Yn + (size_t)r * DD; }

    int t = threadIdx.x;
    int lane = t & 31;
    int warp = t >> 5;

    float2 e = *(const float2*)(src + 2 * t);
    float p = __fadd_rn(__fmul_rn(e.x, e.x), __fmul_rn(e.y, e.y));
    #pragma unroll
    for (int o = 16; o > 0; o >>= 1)
        p = __fadd_rn(p, __shfl_xor_sync(0xffffffffu, p, o));
    if (lane == 0) sw[warp] = p;
    __syncthreads();
    if (warp == 0) {
        float v = (lane < 4) ? sw[lane] : 0.0f;
        #pragma unroll
        for (int o = 16; o > 0; o >>= 1)
            v = __fadd_rn(v, __shfl_xor_sync(0xffffffffu, v, o));
        if (lane == 0)
            smv = fmaxf(__fsqrt_rn(v), 1e-8f);
    }
    __syncthreads();
    float inv = __fdiv_rn(1.0f, smv);
    float2 o;
    o.x = __fmul_rn(e.x, inv);
    o.y = __fmul_rn(e.y, inv);
    *(float2*)(dst + 2 * t) = o;
}

// ---------------------------------------------------------------------------
// Fused SGEMM (128x128 tile, BK=16, fp32) + running per-row top-30.
// Fragment split mapping: thread covers rows {ty*4+i, 64+ty*4+i} and cols
// {tx*4+j, 64+tx*4+j} -> quarter-warp LDS.128 addresses stride 16B ->
// conflict-free. Single ascending-k FMA chain per element (bitwise stable).
// ---------------------------------------------------------------------------
__global__ __launch_bounds__(256, 2)
void simtopk_kernel() {
    extern __shared__ float sm[];
    float* As = sm;                     // [2][BKC][BM]  4096 floats/buf? -> 2*16*128
    float* Bs = sm + 2 * BKC * BM;      // [2][BKC][BN]
    float* Cs = sm;                     // [BM][BN+1] aliases (sync-separated)

    const int t = threadIdx.x;
    const int mbase = blockIdx.x * BM;
    const int sp = blockIdx.y;
    const int tx = t & 15;
    const int ty = t >> 4;

    const int lr = t & 127;
    const int lh = t >> 7;

    const int lrow = t >> 1;            // global-load row (0..127)
    const int lk8  = (t & 1) * 8;       // k-offset of this thread's 8-wide slab

    const int r0 = ty * 4;              // fragment row bases
    const int r1 = 64 + ty * 4;
    const int c0 = tx * 4;              // fragment col bases
    const int c1 = 64 + tx * 4;

    float kv[KSEL];
    int   ki[KSEL];
    #pragma unroll
    for (int j = 0; j < KSEL; j++) { kv[j] = -FLT_MAX; ki[j] = 0x7fffffff; }
    float kth = -FLT_MAX;

    const float* Aptr = g_Xn + (size_t)(mbase + lrow) * DD + lk8;

    #pragma unroll 1
    for (int nt = 0; nt < NYS / BN; nt++) {
        const int nbase = sp * NYS + nt * BN;
        const float* Bptr = g_Yn + (size_t)(nbase + lrow) * DD + lk8;

        float acc[8][8];
        #pragma unroll
        for (int i = 0; i < 8; i++)
            #pragma unroll
            for (int j = 0; j < 8; j++) acc[i][j] = 0.0f;

        // stage 0 fill: each thread loads 2 float4 from A and B
        {
            float4 aa = *(const float4*)(Aptr);
            float4 ab = *(const float4*)(Aptr + 4);
            float4 ba = *(const float4*)(Bptr);
            float4 bb = *(const float4*)(Bptr + 4);
            As[(lk8 + 0) * BM + lrow] = aa.x;
            As[(lk8 + 1) * BM + lrow] = aa.y;
            As[(lk8 + 2) * BM + lrow] = aa.z;
            As[(lk8 + 3) * BM + lrow] = aa.w;
            As[(lk8 + 4) * BM + lrow] = ab.x;
            As[(lk8 + 5) * BM + lrow] = ab.y;
            As[(lk8 + 6) * BM + lrow] = ab.z;
            As[(lk8 + 7) * BM + lrow] = ab.w;
            Bs[(lk8 + 0) * BN + lrow] = ba.x;
            Bs[(lk8 + 1) * BN + lrow] = ba.y;
            Bs[(lk8 + 2) * BN + lrow] = ba.z;
            Bs[(lk8 + 3) * BN + lrow] = ba.w;
            Bs[(lk8 + 4) * BN + lrow] = bb.x;
            Bs[(lk8 + 5) * BN + lrow] = bb.y;
            Bs[(lk8 + 6) * BN + lrow] = bb.z;
            Bs[(lk8 + 7) * BN + lrow] = bb.w;
        }
        __syncthreads();

        #pragma unroll 1
        for (int ksg = 0; ksg < NST; ksg++) {
            float4 naa, nab, nba, nbb;
            const bool more = (ksg + 1 < NST);
            if (more) {
                naa = *(const float4*)(Aptr + (ksg + 1) * BKC);
                nab = *(const float4*)(Aptr + (ksg + 1) * BKC + 4);
                nba = *(const float4*)(Bptr + (ksg + 1) * BKC);
                nbb = *(const float4*)(Bptr + (ksg + 1) * BKC + 4);
            }
            const float* Ac = As + (ksg & 1) * BKC * BM;
            const float* Bc = Bs + (ksg & 1) * BKC * BN;
            #pragma unroll
            for (int kk = 0; kk < BKC; kk++) {
                float a[8], b[8];
                *(float4*)(a)     = *(const float4*)(Ac + kk * BM + r0);
                *(float4*)(a + 4) = *(const float4*)(Ac + kk * BM + r1);
                *(float4*)(b)     = *(const float4*)(Bc + kk * BN + c0);
                *(float4*)(b + 4) = *(const float4*)(Bc + kk * BN + c1);
                #pragma unroll
                for (int i = 0; i < 8; i++)
                    #pragma unroll
                    for (int j = 0; j < 8; j++)
                        acc[i][j] = __fmaf_rn(a[i], b[j], acc[i][j]);
            }
            if (more) {
                float* An = As + ((ksg + 1) & 1) * BKC * BM;
                float* Bn = Bs + ((ksg + 1) & 1) * BKC * BN;
                An[(lk8 + 0) * BM + lrow] = naa.x;
                An[(lk8 + 1) * BM + lrow] = naa.y;
                An[(lk8 + 2) * BM + lrow] = naa.z;
                An[(lk8 + 3) * BM + lrow] = naa.w;
                An[(lk8 + 4) * BM + lrow] = nab.x;
                An[(lk8 + 5) * BM + lrow] = nab.y;
                An[(lk8 + 6) * BM + lrow] = nab.z;
                An[(lk8 + 7) * BM + lrow] = nab.w;
                Bn[(lk8 + 0) * BN + lrow] = nba.x;
                Bn[(lk8 + 1) * BN + lrow] = nba.y;
                Bn[(lk8 + 2) * BN + lrow] = nba.z;
                Bn[(lk8 + 3) * BN + lrow] = nba.w;
                Bn[(lk8 + 4) * BN + lrow] = nbb.x;
                Bn[(lk8 + 5) * BN + lrow] = nbb.y;
                Bn[(lk8 + 6) * BN + lrow] = nbb.z;
                Bn[(lk8 + 7) * BN + lrow] = nbb.w;
            }
            __syncthreads();
        }

        // stage C tile to smem (stride BN+1)
        #pragma unroll
        for (int i = 0; i < 8; i++) {
            int row = (i < 4) ? (r0 + i) : (r1 + i - 4);
            #pragma unroll
            for (int j = 0; j < 8; j++) {
                int col = (j < 4) ? (c0 + j) : (c1 + j - 4);
                Cs[row * (BN + 1) + col] = acc[i][j];
            }
        }
        __syncthreads();

        // running top-k: thread scans 64 candidates of its row (stable order)
        {
            const float* crow = Cs + lr * (BN + 1) + lh * 64;
            const int gbase = nbase + lh * 64;
            #pragma unroll 1
            for (int j = 0; j < 64; j++) {
                float v = crow[j];
                if (v > kth) {
                    int p = KSEL - 1;
                    while (p > 0 && kv[p - 1] < v) {
                        kv[p] = kv[p - 1];
                        ki[p] = ki[p - 1];
                        p--;
                    }
                    kv[p] = v;
                    ki[p] = gbase + j;
                    kth = kv[KSEL - 1];
                }
            }
        }
        __syncthreads();   // before next tile overwrites Cs/As/Bs
    }

    // emit partial sorted list
    {
        const int row = mbase + lr;
        const size_t base = ((size_t)(row * SPLITS + sp) * 2 + lh) * KSEL;
        #pragma unroll 1
        for (int j = 0; j < KSEL; j++) {
            g_pv[base + j] = kv[j];
            g_pi[base + j] = ki[j];
        }
    }
}

// ---------------------------------------------------------------------------
// Merge 6 sorted partial lists per row -> final top-30; write values,u,v.
// Tie-break identical to jax.lax.top_k: value desc, index asc (stable).
// ---------------------------------------------------------------------------
__global__ void merge_kernel(float* __restrict__ out) {
    int r = blockIdx.x * blockDim.x + threadIdx.x;
    if (r >= NX) return;
    float mv[KSEL];
    int   mi[KSEL];
    #pragma unroll
    for (int j = 0; j < KSEL; j++) { mv[j] = -FLT_MAX; mi[j] = 0x7fffffff; }

    for (int l = 0; l < SPLITS * 2; l++) {
        const size_t base = ((size_t)r * SPLITS * 2 + l) * KSEL;
        for (int e = 0; e < KSEL; e++) {
            float v = g_pv[base + e];
            int idx = g_pi[base + e];
            float lv = mv[KSEL - 1];
            int   li = mi[KSEL - 1];
            bool better = (v > lv) || (v == lv && idx < li);
            if (!better) break;   // sorted list: rest can't qualify
            int p = KSEL - 1;
            while (p > 0 && (v > mv[p - 1] || (v == mv[p - 1] && idx < mi[p - 1]))) {
                mv[p] = mv[p - 1];
                mi[p] = mi[p - 1];
                p--;
            }
            mv[p] = v;
            mi[p] = idx;
        }
    }

    const size_t NK = (size_t)NX * KSEL;
    #pragma unroll 1
    for (int j = 0; j < KSEL; j++) {
        out[(size_t)r * KSEL + j]          = mv[j];        // values
        out[NK + (size_t)r * KSEL + j]     = (float)r;     // u
        out[2 * NK + (size_t)r * KSEL + j] = (float)mi[j]; // v
    }
}

extern "C" void kernel_launch(void* const* d_in, const int* in_sizes, int n_in,
                              void* d_out, int out_size) {
    const float* X = (const float*)d_in[0];
    const float* Y = (const float*)d_in[1];
    float* out = (float*)d_out;

    // smem: max(As+Bs double buffers, Cs) = max(32KB, 66KB) = 66048
    const int smem_bytes = BM * (BN + 1) * 4;
    cudaFuncSetAttribute(simtopk_kernel,
                         cudaFuncAttributeMaxDynamicSharedMemorySize, smem_bytes);

    norm_kernel<<<NX + NYTOT, 128>>>(X, Y);

    dim3 grid(NX / BM, SPLITS);
    simtopk_kernel<<<grid, 256, smem_bytes>>>();

    merge_kernel<<<(NX + 255) / 256, 256>>>(out);
}